// round 2
// baseline (speedup 1.0000x reference)
#include <cuda_runtime.h>

#define TT 32
#define PP 16
#define NN 65536
#define HH 128
#define NTHREADS 128
#define NBLOCKS 256   // 256 blocks * 128 threads * 2 points = 65536

#define OFF_ARG (TT * NN * 3)      // 6291456
#define OFF_TL  (OFF_ARG + NN)     // 6356992

__device__ __forceinline__ unsigned long long packrep(float a) {
    unsigned long long r;
    asm("mov.b64 %0, {%1, %1};" : "=l"(r) : "f"(a));
    return r;
}
__device__ __forceinline__ void fma2(unsigned long long& d, unsigned long long a, unsigned long long b) {
    asm("fma.rn.f32x2 %0, %1, %2, %0;" : "+l"(d) : "l"(a), "l"(b));
}
__device__ __forceinline__ void unpack2(unsigned long long v, float& lo, float& hi) {
    asm("mov.b64 {%0, %1}, %2;" : "=f"(lo), "=f"(hi) : "l"(v));
}

__global__ void __launch_bounds__(NTHREADS) fused_kernel(
    const float* __restrict__ cano, const float* __restrict__ w1,
    const float* __restrict__ b1, const float* __restrict__ w2,
    const float* __restrict__ b2, const float* __restrict__ p6d,
    const float* __restrict__ pt, const float* __restrict__ gum,
    float* __restrict__ out)
{
    __shared__ float4 s_w1[HH];                        // w1 row + b1
    __shared__ __align__(16) float2 s_w2p[HH][8];      // w2 packed over p-pairs
    __shared__ float2 s_b2p[8];
    __shared__ __align__(16) float s_R[TT * PP][12];   // R rows + t

    const int tid = threadIdx.x;

    // ---- stage weights into shared memory ----
    s_w1[tid] = make_float4(w1[3 * tid], w1[3 * tid + 1], w1[3 * tid + 2], b1[tid]);

    #pragma unroll
    for (int k = 0; k < 8; k++) {
        int idx = k * NTHREADS + tid;     // 0..1023
        int h = idx & (HH - 1);
        int pp = idx >> 7;                // 0..7
        s_w2p[h][pp] = make_float2(w2[(2 * pp) * HH + h], w2[(2 * pp + 1) * HH + h]);
    }
    if (tid < 8) s_b2p[tid] = make_float2(b2[2 * tid], b2[2 * tid + 1]);

    // ---- per-block rotation table (tiny, redundant across blocks by design) ----
    #pragma unroll
    for (int k = 0; k < 4; k++) {
        int e = k * NTHREADS + tid;       // 0..511 = t*16+p
        float a1x = p6d[e * 6 + 0], a1y = p6d[e * 6 + 1], a1z = p6d[e * 6 + 2];
        float a2x = p6d[e * 6 + 3], a2y = p6d[e * 6 + 4], a2z = p6d[e * 6 + 5];
        float inv = rsqrtf(a1x * a1x + a1y * a1y + a1z * a1z);
        float b1x = a1x * inv, b1y = a1y * inv, b1z = a1z * inv;
        float d = b1x * a2x + b1y * a2y + b1z * a2z;
        float cx = a2x - d * b1x, cy = a2y - d * b1y, cz = a2z - d * b1z;
        float inv2 = rsqrtf(cx * cx + cy * cy + cz * cz);
        float b2x = cx * inv2, b2y = cy * inv2, b2z = cz * inv2;
        float b3x = b1y * b2z - b1z * b2y;
        float b3y = b1z * b2x - b1x * b2z;
        float b3z = b1x * b2y - b1y * b2x;
        float t0 = pt[e * 3 + 0], t1 = pt[e * 3 + 1], t2 = pt[e * 3 + 2];
        float* r = s_R[e];
        r[0] = b1x; r[1] = b1y; r[2] = b1z;
        r[3] = b2x; r[4] = b2y; r[5] = b2z;
        r[6] = b3x; r[7] = b3y; r[8] = b3z;
        r[9] = t0;  r[10] = t1; r[11] = t2;
        if (blockIdx.x == 0) {
            // trans_list[t][p] = [[R | t],[0 0 0 1]]
            float* o = out + OFF_TL + e * 16;
            o[0] = b1x; o[1] = b1y; o[2]  = b1z; o[3]  = t0;
            o[4] = b2x; o[5] = b2y; o[6]  = b2z; o[7]  = t1;
            o[8] = b3x; o[9] = b3y; o[10] = b3z; o[11] = t2;
            o[12] = 0.f; o[13] = 0.f; o[14] = 0.f; o[15] = 1.f;
        }
    }
    __syncthreads();

    // ---- two points per thread ----
    const int i = blockIdx.x * NTHREADS + tid;
    const int nA = 2 * i, nB = nA + 1;
    const float xAx = cano[nA * 3], xAy = cano[nA * 3 + 1], xAz = cano[nA * 3 + 2];
    const float xBx = cano[nB * 3], xBy = cano[nB * 3 + 1], xBz = cano[nB * 3 + 2];

    unsigned long long segA[8], segB[8];
    #pragma unroll
    for (int k = 0; k < 8; k++) {
        unsigned long long bb = *reinterpret_cast<const unsigned long long*>(&s_b2p[k]);
        segA[k] = bb; segB[k] = bb;
    }

    // MLP: h = relu(x@w1^T + b1); seg = h@w2^T + b2, packed f32x2 over p-pairs
    #pragma unroll 8
    for (int h = 0; h < HH; h++) {
        float4 w = s_w1[h];
        float hA = fmaxf(fmaf(xAx, w.x, fmaf(xAy, w.y, fmaf(xAz, w.z, w.w))), 0.0f);
        float hB = fmaxf(fmaf(xBx, w.x, fmaf(xBy, w.y, fmaf(xBz, w.z, w.w))), 0.0f);
        unsigned long long hA2 = packrep(hA);
        unsigned long long hB2 = packrep(hB);
        const ulonglong2* wp = reinterpret_cast<const ulonglong2*>(&s_w2p[h][0]);
        ulonglong2 q0 = wp[0], q1 = wp[1], q2 = wp[2], q3 = wp[3];
        fma2(segA[0], hA2, q0.x); fma2(segB[0], hB2, q0.x);
        fma2(segA[1], hA2, q0.y); fma2(segB[1], hB2, q0.y);
        fma2(segA[2], hA2, q1.x); fma2(segB[2], hB2, q1.x);
        fma2(segA[3], hA2, q1.y); fma2(segB[3], hB2, q1.y);
        fma2(segA[4], hA2, q2.x); fma2(segB[4], hB2, q2.x);
        fma2(segA[5], hA2, q2.y); fma2(segB[5], hB2, q2.y);
        fma2(segA[6], hA2, q3.x); fma2(segB[6], hB2, q3.x);
        fma2(segA[7], hA2, q3.y); fma2(segB[7], hB2, q3.y);
    }

    float sA[16], sB[16];
    #pragma unroll
    for (int k = 0; k < 8; k++) {
        unpack2(segA[k], sA[2 * k], sA[2 * k + 1]);
        unpack2(segB[k], sB[2 * k], sB[2 * k + 1]);
    }

    // argmax(seg) (output 2), first-occurrence semantics
    int iaA = 0, iaB = 0;
    float mA = sA[0], mB = sB[0];
    #pragma unroll
    for (int p = 1; p < PP; p++) {
        if (sA[p] > mA) { mA = sA[p]; iaA = p; }
        if (sB[p] > mB) { mB = sB[p]; iaB = p; }
    }
    out[OFF_ARG + nA] = (float)iaA;
    out[OFF_ARG + nB] = (float)iaB;

    // selection = argmax(seg + gumbel)  (== argmax of gumbel-softmax)
    const float4* g4A = reinterpret_cast<const float4*>(gum + (size_t)nA * PP);
    const float4* g4B = reinterpret_cast<const float4*>(gum + (size_t)nB * PP);
    int selA = 0, selB = 0;
    float vmA = -1e30f, vmB = -1e30f;
    #pragma unroll
    for (int q = 0; q < 4; q++) {
        float4 ga = g4A[q], gb = g4B[q];
        float a0 = sA[4 * q + 0] + ga.x, a1 = sA[4 * q + 1] + ga.y;
        float a2 = sA[4 * q + 2] + ga.z, a3 = sA[4 * q + 3] + ga.w;
        float c0 = sB[4 * q + 0] + gb.x, c1 = sB[4 * q + 1] + gb.y;
        float c2 = sB[4 * q + 2] + gb.z, c3 = sB[4 * q + 3] + gb.w;
        if (a0 > vmA) { vmA = a0; selA = 4 * q + 0; }
        if (a1 > vmA) { vmA = a1; selA = 4 * q + 1; }
        if (a2 > vmA) { vmA = a2; selA = 4 * q + 2; }
        if (a3 > vmA) { vmA = a3; selA = 4 * q + 3; }
        if (c0 > vmB) { vmB = c0; selB = 4 * q + 0; }
        if (c1 > vmB) { vmB = c1; selB = 4 * q + 1; }
        if (c2 > vmB) { vmB = c2; selB = 4 * q + 2; }
        if (c3 > vmB) { vmB = c3; selB = 4 * q + 3; }
    }

    // pc_out[t,n,:] = R[t,sel] @ x + t[t,sel]
    #pragma unroll 4
    for (int t = 0; t < TT; t++) {
        const float4* RA = reinterpret_cast<const float4*>(s_R[t * PP + selA]);
        float4 a0 = RA[0], a1 = RA[1], a2 = RA[2];
        float oA0 = fmaf(xAx, a0.x, fmaf(xAy, a0.y, fmaf(xAz, a0.z, a2.y)));
        float oA1 = fmaf(xAx, a0.w, fmaf(xAy, a1.x, fmaf(xAz, a1.y, a2.z)));
        float oA2 = fmaf(xAx, a1.z, fmaf(xAy, a1.w, fmaf(xAz, a2.x, a2.w)));
        const float4* RB = reinterpret_cast<const float4*>(s_R[t * PP + selB]);
        float4 c0 = RB[0], c1 = RB[1], c2 = RB[2];
        float oB0 = fmaf(xBx, c0.x, fmaf(xBy, c0.y, fmaf(xBz, c0.z, c2.y)));
        float oB1 = fmaf(xBx, c0.w, fmaf(xBy, c1.x, fmaf(xBz, c1.y, c2.z)));
        float oB2 = fmaf(xBx, c1.z, fmaf(xBy, c1.w, fmaf(xBz, c2.x, c2.w)));
        float2* dst = reinterpret_cast<float2*>(out + (size_t)(t * NN + nA) * 3);
        dst[0] = make_float2(oA0, oA1);
        dst[1] = make_float2(oA2, oB0);
        dst[2] = make_float2(oB1, oB2);
    }
}

extern "C" void kernel_launch(void* const* d_in, const int* in_sizes, int n_in,
                              void* d_out, int out_size) {
    (void)in_sizes; (void)n_in; (void)out_size;
    fused_kernel<<<NBLOCKS, NTHREADS>>>(
        (const float*)d_in[0],  // cano_pc
        (const float*)d_in[1],  // w1
        (const float*)d_in[2],  // b1
        (const float*)d_in[3],  // w2
        (const float*)d_in[4],  // b2
        (const float*)d_in[5],  // proposal_6d
        (const float*)d_in[6],  // proposal_t
        (const float*)d_in[7],  // gumbel
        (float*)d_out);
}